// round 9
// baseline (speedup 1.0000x reference)
#include <cuda_runtime.h>

// B=256, N=1024, D=512, K=2.
// out[row][k] = softmax_k( exp(logit_scale) * dot(x[row], tf[k]/||tf[k]||) )
// rows = 262144. Persistent 592-block kernel (1 wave) + dynamic work stealing:
// 8 partitions x 1024 chunks of 32 rows; blocks grab chunks via monotonic
// self-resetting atomic counters so fast SMs take more work (beats the ~1.10
// between-SM rate-spread floor of a static persistent split).

#define D 512
#define ROWS (256 * 1024)
#define GRID 592
#define TPB 256

#define NPART 8
#define BLK_PER_PART (GRID / NPART)        // 74
#define PART_ROWS (ROWS / NPART)           // 32768
#define CHUNK_ROWS 32                      // 4 rows per warp per grab
#define NCHUNK (PART_ROWS / CHUNK_ROWS)    // 1024

// One counter per partition, 128B apart (distinct L2 banks). Zero-initialized
// at module load; self-resets to 0 at the end of every launch.
__device__ unsigned g_ctr[NPART * 32];

__global__ __launch_bounds__(TPB, 4)
void prompts_kernel(const float4* __restrict__ x,
                    const float4* __restrict__ tf,   // [2*512] floats as float4
                    const float*  __restrict__ ls,
                    float2* __restrict__ out) {
    const int lane = threadIdx.x & 31;
    const int wloc = threadIdx.x >> 5;       // warp within block, 0..7
    const unsigned FULL = 0xffffffffu;

    // ---- per-warp weight setup: load tf, normalize, fold exp(logit_scale) ----
    float4 w0[4], w1[4];
    float n0 = 0.f, n1 = 0.f;
    #pragma unroll
    for (int p = 0; p < 4; p++) {
        w0[p] = tf[p * 32 + lane];           // prompt 0: floats [0,512)
        w1[p] = tf[128 + p * 32 + lane];     // prompt 1: floats [512,1024)
        n0 += w0[p].x * w0[p].x + w0[p].y * w0[p].y + w0[p].z * w0[p].z + w0[p].w * w0[p].w;
        n1 += w1[p].x * w1[p].x + w1[p].y * w1[p].y + w1[p].z * w1[p].z + w1[p].w * w1[p].w;
    }
    #pragma unroll
    for (int o = 16; o; o >>= 1) {
        n0 += __shfl_xor_sync(FULL, n0, o);
        n1 += __shfl_xor_sync(FULL, n1, o);
    }
    const float scale = __expf(ls[0]);
    const float c0 = rsqrtf(n0) * scale;
    const float c1 = rsqrtf(n1) * scale;
    #pragma unroll
    for (int p = 0; p < 4; p++) {
        w0[p].x *= c0; w0[p].y *= c0; w0[p].z *= c0; w0[p].w *= c0;
        w1[p].x *= c1; w1[p].y *= c1; w1[p].z *= c1; w1[p].w *= c1;
    }

    // ---- work-stealing loop ----
    const int part = blockIdx.x & (NPART - 1);
    unsigned* ctr = &g_ctr[part * 32];
    const int row_base_part = part * PART_ROWS;

    __shared__ unsigned s_chunk;
    if (threadIdx.x == 0) s_chunk = atomicAdd(ctr, 1u);
    __syncthreads();

    for (;;) {
        const unsigned cur = s_chunk;
        __syncthreads();                       // all threads have read s_chunk
        if (cur >= NCHUNK) {
            // Exactly one failing grab per block; values NCHUNK..NCHUNK+73.
            // The block holding the last one resets the counter for the next launch.
            if (threadIdx.x == 0 && cur == NCHUNK + BLK_PER_PART - 1)
                atomicExch(ctr, 0u);
            return;
        }
        if (threadIdx.x == 0) s_chunk = atomicAdd(ctr, 1u);  // prefetch next chunk

        // process 4 consecutive rows for this warp
        int r0 = row_base_part + (int)cur * CHUNK_ROWS + wloc * 4;
        const float4* xr = x + (size_t)r0 * (D / 4) + lane;
        #pragma unroll 1
        for (int i = 0; i < 4; i++, xr += (D / 4)) {
            float s0 = 0.f, s1 = 0.f;
            #pragma unroll
            for (int p = 0; p < 4; p++) {
                float4 v = __ldcs(xr + p * 32);
                s0 = fmaf(v.x, w0[p].x, s0);
                s0 = fmaf(v.y, w0[p].y, s0);
                s0 = fmaf(v.z, w0[p].z, s0);
                s0 = fmaf(v.w, w0[p].w, s0);
                s1 = fmaf(v.x, w1[p].x, s1);
                s1 = fmaf(v.y, w1[p].y, s1);
                s1 = fmaf(v.z, w1[p].z, s1);
                s1 = fmaf(v.w, w1[p].w, s1);
            }
            #pragma unroll
            for (int o = 16; o; o >>= 1) {
                s0 += __shfl_xor_sync(FULL, s0, o);
                s1 += __shfl_xor_sync(FULL, s1, o);
            }
            if (lane == 0) {
                float m  = fmaxf(s0, s1);
                float e0 = __expf(s0 - m);
                float e1 = __expf(s1 - m);
                float inv = __fdividef(1.f, e0 + e1);
                out[r0 + i] = make_float2(e0 * inv, e1 * inv);
            }
        }
        __syncthreads();   // tid0's s_chunk update visible before next read
    }
}

extern "C" void kernel_launch(void* const* d_in, const int* in_sizes, int n_in,
                              void* d_out, int out_size) {
    const float* x  = (const float*)d_in[0];   // [256,1024,512] f32
    const float* tf = (const float*)d_in[1];   // [2,512] f32
    const float* ls = (const float*)d_in[2];   // [1] f32
    float2* out = (float2*)d_out;              // [262144,2] f32

    prompts_kernel<<<GRID, TPB>>>((const float4*)x, (const float4*)tf, ls, out);
}